// round 1
// baseline (speedup 1.0000x reference)
#include <cuda_runtime.h>
#include <math.h>

#define NN 12288
#define EE 393216
#define ET (EE + NN)

// ---------------- scratch (static __device__, no allocs) ----------------
__device__ int   g_degi[NN];
__device__ int   g_tmp[NN];
__device__ int   g_rowptr[NN + 1];
__device__ float g_dinv[NN];
__device__ int   g_cidx[ET];
__device__ float g_cval[ET];

__device__ float g_P1[NN * 128];   // [P1 | P1_cf]
__device__ float g_H1[NN * 128];   // relu(agg P1)+b1 for both
__device__ float g_Q [NN * 128];   // [H1a@W2 | H1b@W2]
__device__ float g_Z [NN * 128];   // [z | z_cf]
__device__ float g_ZS[NN * 96];    // [z_s | z_ns | z_s_cf]
__device__ float g_AZ[NN * 96];    // agg of ZS
__device__ float g_HD[NN * 192];   // [relu d1(z_s) | relu d2(z_ns) | relu d1(z_s_cf)]
__device__ float g_AH[NN * 192];   // agg of HD
__device__ float g_HS[NN * 64];    // hs

// ---------------- graph build ----------------
__global__ void k_zero2(void) {
    int i = blockIdx.x * blockDim.x + threadIdx.x;
    if (i < NN) g_degi[i] = 0;
    else if (i < 2 * NN) g_tmp[i - NN] = 0;
}

__global__ void k_deg(const int* __restrict__ ei) {
    int i = blockIdx.x * blockDim.x + threadIdx.x;
    if (i < EE) atomicAdd(&g_degi[ei[EE + i]], 1);
}

__global__ void k_dinv(void) {
    int i = blockIdx.x * blockDim.x + threadIdx.x;
    if (i < NN) g_dinv[i] = rsqrtf((float)(g_degi[i] + 1));
}

__global__ void k_scan(void) {  // 1 block, 1024 threads, 12 elems each
    __shared__ int sums[1024];
    int t = threadIdx.x;
    int base = t * 12;
    int local[12];
    int s = 0;
#pragma unroll
    for (int i = 0; i < 12; i++) { local[i] = g_degi[base + i] + 1; s += local[i]; }
    sums[t] = s;
    __syncthreads();
    for (int off = 1; off < 1024; off <<= 1) {
        int v = (t >= off) ? sums[t - off] : 0;
        __syncthreads();
        sums[t] += v;
        __syncthreads();
    }
    int excl = (t == 0) ? 0 : sums[t - 1];
#pragma unroll
    for (int i = 0; i < 12; i++) { g_rowptr[base + i] = excl; excl += local[i]; }
    if (t == 1023) g_rowptr[NN] = excl;
}

__global__ void k_fill(const int* __restrict__ ei) {
    int i = blockIdx.x * blockDim.x + threadIdx.x;
    if (i < EE) {
        int s = ei[i], d = ei[EE + i];
        int p = g_rowptr[d] + atomicAdd(&g_tmp[d], 1);
        g_cidx[p] = s;
        g_cval[p] = g_dinv[s] * g_dinv[d];
    } else if (i < ET) {
        int nid = i - EE;
        int p = g_rowptr[nid] + atomicAdd(&g_tmp[nid], 1);
        g_cidx[p] = nid;
        g_cval[p] = g_dinv[nid] * g_dinv[nid];
    }
}

// ---------------- CSR SpMM: out[n,f] = sum_e val*H[src,f]  (+bias,relu) ----------------
template <int VT>
__global__ __launch_bounds__(256) void k_spmm(const float* __restrict__ H,
                                              float* __restrict__ out,
                                              const float* __restrict__ bias,
                                              int relu) {
    const int F = VT * 32;
    int warp = (blockIdx.x * blockDim.x + threadIdx.x) >> 5;
    int lane = threadIdx.x & 31;
    if (warp >= NN) return;
    float acc[VT];
#pragma unroll
    for (int i = 0; i < VT; i++) acc[i] = 0.f;
    int p0 = g_rowptr[warp], p1 = g_rowptr[warp + 1];
    for (int p = p0; p < p1; ++p) {
        int s = g_cidx[p];
        float v = g_cval[p];
        const float* hr = H + s * F;
#pragma unroll
        for (int i = 0; i < VT; i++) acc[i] += v * __ldg(hr + lane + i * 32);
    }
    float* o = out + warp * F;
#pragma unroll
    for (int i = 0; i < VT; i++) {
        float r = acc[i];
        if (bias) r += bias[(lane + i * 32) & 63];
        if (relu) r = fmaxf(r, 0.f);
        o[lane + i * 32] = r;
    }
}

// ---------------- generic small GEMM: C = act(A[:,aoff:aoff+K] @ B + bias) ----------------
// block: 128 rows x 64 cols, 256 threads, thread tile 8x4
__global__ __launch_bounds__(256) void k_gemm(const float* __restrict__ A, int lda, int aoff,
                                              const float* __restrict__ B, int ldb, int K,
                                              float* __restrict__ C, int ldc, int coff,
                                              const float* __restrict__ bias, int relu) {
    __shared__ float As[128 * 36];
    __shared__ float Bs[32 * 64];
    int r0 = blockIdx.x * 128;
    int c0 = blockIdx.y * 64;
    int t = threadIdx.x;
    int tx = t & 15, ty = t >> 4;
    float acc[8][4];
#pragma unroll
    for (int i = 0; i < 8; i++)
#pragma unroll
        for (int j = 0; j < 4; j++) acc[i][j] = 0.f;

    for (int kt = 0; kt < K; kt += 32) {
#pragma unroll
        for (int it = 0; it < 4; ++it) {
            int li = t + it * 256;
            int m = li >> 3;
            int kv = (li & 7) << 2;
            float4 v = *(const float4*)(A + (r0 + m) * lda + aoff + kt + kv);
            *(float4*)&As[m * 36 + kv] = v;
        }
#pragma unroll
        for (int it = 0; it < 2; ++it) {
            int li = t + it * 256;
            int kk = li >> 4;
            int nv = (li & 15) << 2;
            float4 v = *(const float4*)(B + (kt + kk) * ldb + c0 + nv);
            *(float4*)&Bs[kk * 64 + nv] = v;
        }
        __syncthreads();
#pragma unroll
        for (int k4 = 0; k4 < 32; k4 += 4) {
            float4 a4[8];
#pragma unroll
            for (int i = 0; i < 8; i++) a4[i] = *(const float4*)&As[(ty * 8 + i) * 36 + k4];
#pragma unroll
            for (int kk = 0; kk < 4; kk++) {
                float4 b = *(const float4*)&Bs[(k4 + kk) * 64 + tx * 4];
#pragma unroll
                for (int i = 0; i < 8; i++) {
                    float av = (kk == 0) ? a4[i].x : (kk == 1) ? a4[i].y : (kk == 2) ? a4[i].z : a4[i].w;
                    acc[i][0] += av * b.x;
                    acc[i][1] += av * b.y;
                    acc[i][2] += av * b.z;
                    acc[i][3] += av * b.w;
                }
            }
        }
        __syncthreads();
    }
    float bv[4] = {0.f, 0.f, 0.f, 0.f};
    if (bias) {
#pragma unroll
        for (int j = 0; j < 4; j++) bv[j] = bias[c0 + tx * 4 + j];
    }
#pragma unroll
    for (int i = 0; i < 8; i++) {
        float4 v;
        v.x = acc[i][0] + bv[0];
        v.y = acc[i][1] + bv[1];
        v.z = acc[i][2] + bv[2];
        v.w = acc[i][3] + bv[3];
        if (relu) {
            v.x = fmaxf(v.x, 0.f); v.y = fmaxf(v.y, 0.f);
            v.z = fmaxf(v.z, 0.f); v.w = fmaxf(v.w, 0.f);
        }
        *(float4*)(C + (r0 + ty * 8 + i) * ldc + coff + c0 + tx * 4) = v;
    }
}

// ---------------- elementwise helpers ----------------
__global__ void k_p1cf(const float* __restrict__ x, const float* __restrict__ W1) {
    int i = blockIdx.x * blockDim.x + threadIdx.x;
    if (i >= NN * 64) return;
    int r = i >> 6, m = i & 63;
    g_P1[r * 128 + 64 + m] = g_P1[r * 128 + m] + (1.f - 2.f * x[r * 256]) * W1[m];
}

__global__ void k_zsbuild(float* __restrict__ o_zs, float* __restrict__ o_zns) {
    int i = blockIdx.x * blockDim.x + threadIdx.x;
    if (i >= NN * 32) return;
    int r = i >> 5, c = i & 31;
    float zs   = g_Z[r * 128 + c];
    float zns  = g_Z[r * 128 + 32 + c];
    float zscf = g_Z[r * 128 + 64 + c];
    g_ZS[r * 96 + c] = zs;
    g_ZS[r * 96 + 32 + c] = zns;
    g_ZS[r * 96 + 64 + c] = zscf;
    o_zs[r * 32 + c] = zs;
    o_zns[r * 32 + c] = zns;
}

// ---------------- symmetric rank-64 SYRK: C = H H^T  (12288x12288, K=64) ----------------
// triangular block grid (4656 blocks), tile 128x128, thread 8x8; off-diag blocks
// write both the tile and its transpose.
__global__ __launch_bounds__(256, 2) void k_syrk(const float* __restrict__ H,
                                                 float* __restrict__ C) {
    extern __shared__ float sm[];
    float* As = sm;               // natural layout: As[m*68 + k], 128x64
    float* Bs = sm + 128 * 68;    // transposed:     Bs[k*132 + m], 64x128

    int t = blockIdx.x;
    float bf = 96.5f - sqrtf(96.5f * 96.5f - 2.0f * (float)t);
    int br = (int)bf;
    if (br < 0) br = 0;
    if (br > 95) br = 95;
    while (96 * br - (br * (br - 1)) / 2 > t) --br;
    while (96 * (br + 1) - ((br + 1) * br) / 2 <= t) ++br;
    int bc = br + (t - (96 * br - (br * (br - 1)) / 2));
    int r0 = br * 128, c0 = bc * 128;

    int tid = threadIdx.x;
#pragma unroll
    for (int it = 0; it < 8; ++it) {   // A tile, coalesced, natural
        int li = tid + it * 256;
        int m = li >> 4;
        int kv = (li & 15) << 2;
        float4 v = *(const float4*)(H + (r0 + m) * 64 + kv);
        *(float4*)&As[m * 68 + kv] = v;
    }
#pragma unroll
    for (int it = 0; it < 8; ++it) {   // B tile, transposed, conflict-free stores
        int m = tid & 127;
        int kvg = (tid >> 7) + 2 * it;
        float4 v = *(const float4*)(H + (c0 + m) * 64 + kvg * 4);
        Bs[(kvg * 4 + 0) * 132 + m] = v.x;
        Bs[(kvg * 4 + 1) * 132 + m] = v.y;
        Bs[(kvg * 4 + 2) * 132 + m] = v.z;
        Bs[(kvg * 4 + 3) * 132 + m] = v.w;
    }
    __syncthreads();

    int tx = tid & 15, ty = tid >> 4;
    float acc[8][8];
#pragma unroll
    for (int i = 0; i < 8; i++)
#pragma unroll
        for (int j = 0; j < 8; j++) acc[i][j] = 0.f;

#pragma unroll 2
    for (int k4 = 0; k4 < 64; k4 += 4) {
        float4 a4[8];
#pragma unroll
        for (int i = 0; i < 8; i++) a4[i] = *(const float4*)&As[(ty * 8 + i) * 68 + k4];
#pragma unroll
        for (int kk = 0; kk < 4; kk++) {
            int k = k4 + kk;
            float4 b0 = *(const float4*)&Bs[k * 132 + tx * 8];
            float4 b1 = *(const float4*)&Bs[k * 132 + tx * 8 + 4];
#pragma unroll
            for (int i = 0; i < 8; i++) {
                float av = (kk == 0) ? a4[i].x : (kk == 1) ? a4[i].y : (kk == 2) ? a4[i].z : a4[i].w;
                acc[i][0] += av * b0.x; acc[i][1] += av * b0.y;
                acc[i][2] += av * b0.z; acc[i][3] += av * b0.w;
                acc[i][4] += av * b1.x; acc[i][5] += av * b1.y;
                acc[i][6] += av * b1.z; acc[i][7] += av * b1.w;
            }
        }
    }

#pragma unroll
    for (int i = 0; i < 8; i++) {        // normal tile
        int row = r0 + ty * 8 + i;
        float4 v0 = make_float4(acc[i][0], acc[i][1], acc[i][2], acc[i][3]);
        float4 v1 = make_float4(acc[i][4], acc[i][5], acc[i][6], acc[i][7]);
        *(float4*)(C + row * NN + c0 + tx * 8) = v0;
        *(float4*)(C + row * NN + c0 + tx * 8 + 4) = v1;
    }
    if (br != bc) {                      // mirrored tile
#pragma unroll
        for (int j = 0; j < 8; j++) {
            int row = c0 + tx * 8 + j;
            float4 w0 = make_float4(acc[0][j], acc[1][j], acc[2][j], acc[3][j]);
            float4 w1 = make_float4(acc[4][j], acc[5][j], acc[6][j], acc[7][j]);
            *(float4*)(C + row * NN + r0 + ty * 8) = w0;
            *(float4*)(C + row * NN + r0 + ty * 8 + 4) = w1;
        }
    }
}

// ---------------- launch ----------------
extern "C" void kernel_launch(void* const* d_in, const int* in_sizes, int n_in,
                              void* d_out, int out_size) {
    const float* x      = (const float*)d_in[0];
    const int*   ei     = (const int*)d_in[1];
    const float* enc_W1 = (const float*)d_in[2];
    const float* enc_b1 = (const float*)d_in[3];
    const float* enc_W2 = (const float*)d_in[4];
    const float* enc_b2 = (const float*)d_in[5];
    const float* d1_W1  = (const float*)d_in[6];
    const float* d1_b1  = (const float*)d_in[7];
    const float* d1_W2  = (const float*)d_in[8];
    const float* d1_b2  = (const float*)d_in[9];
    const float* d2_W1  = (const float*)d_in[10];
    const float* d2_b1  = (const float*)d_in[11];
    const float* d2_W2  = (const float*)d_in[12];
    const float* d2_b2  = (const float*)d_in[13];
    const float* s_W    = (const float*)d_in[14];
    const float* s_b    = (const float*)d_in[15];

    float* out     = (float*)d_out;
    float* o_zs    = out;
    float* o_zns   = out + NN * 32;
    float* o_xs    = out + NN * 64;
    float* o_xns   = o_xs + NN * 256;
    float* o_xscf  = o_xns + NN * 256;
    float* o_s     = o_xscf + NN * 256;

    float *p_P1, *p_H1, *p_Q, *p_Z, *p_ZS, *p_AZ, *p_HD, *p_AH, *p_HS;
    cudaGetSymbolAddress((void**)&p_P1, g_P1);
    cudaGetSymbolAddress((void**)&p_H1, g_H1);
    cudaGetSymbolAddress((void**)&p_Q,  g_Q);
    cudaGetSymbolAddress((void**)&p_Z,  g_Z);
    cudaGetSymbolAddress((void**)&p_ZS, g_ZS);
    cudaGetSymbolAddress((void**)&p_AZ, g_AZ);
    cudaGetSymbolAddress((void**)&p_HD, g_HD);
    cudaGetSymbolAddress((void**)&p_AH, g_AH);
    cudaGetSymbolAddress((void**)&p_HS, g_HS);

    cudaFuncSetAttribute(k_syrk, cudaFuncAttributeMaxDynamicSharedMemorySize,
                         (128 * 68 + 64 * 132) * (int)sizeof(float));

    // graph normalization + CSR
    k_zero2<<<(2 * NN + 255) / 256, 256>>>();
    k_deg<<<(EE + 255) / 256, 256>>>(ei);
    k_dinv<<<(NN + 255) / 256, 256>>>();
    k_scan<<<1, 1024>>>();
    k_fill<<<(ET + 255) / 256, 256>>>(ei);

    // encoder layer 1
    k_gemm<<<dim3(96, 1), 256>>>(x, 256, 0, enc_W1, 64, 256, p_P1, 128, 0, nullptr, 0);
    k_p1cf<<<(NN * 64 + 255) / 256, 256>>>(x, enc_W1);
    k_spmm<4><<<NN / 8, 256>>>(p_P1, p_H1, enc_b1, 1);

    // encoder layer 2
    k_gemm<<<dim3(96, 1), 256>>>(p_H1, 128, 0,  enc_W2, 64, 64, p_Q, 128, 0,  nullptr, 0);
    k_gemm<<<dim3(96, 1), 256>>>(p_H1, 128, 64, enc_W2, 64, 64, p_Q, 128, 64, nullptr, 0);
    k_spmm<4><<<NN / 8, 256>>>(p_Q, p_Z, enc_b2, 0);

    // split + batched z aggregation
    k_zsbuild<<<(NN * 32 + 255) / 256, 256>>>(o_zs, o_zns);
    k_spmm<3><<<NN / 8, 256>>>(p_ZS, p_AZ, nullptr, 0);

    // decoder first convs + structure head
    k_gemm<<<dim3(96, 1), 256>>>(p_AZ, 96, 0,  d1_W1, 64, 32, p_HD, 192, 0,   d1_b1, 1);
    k_gemm<<<dim3(96, 1), 256>>>(p_AZ, 96, 32, d2_W1, 64, 32, p_HD, 192, 64,  d2_b1, 1);
    k_gemm<<<dim3(96, 1), 256>>>(p_AZ, 96, 64, d1_W1, 64, 32, p_HD, 192, 128, d1_b1, 1);
    k_gemm<<<dim3(96, 1), 256>>>(p_AZ, 96, 32, s_W,   64, 32, p_HS, 64, 0,    s_b,   0);

    // decoder second convs (aggregate at 64, then widen to 256)
    k_spmm<6><<<NN / 8, 256>>>(p_HD, p_AH, nullptr, 0);
    k_gemm<<<dim3(96, 4), 256>>>(p_AH, 192, 0,   d1_W2, 256, 64, o_xs,   256, 0, d1_b2, 0);
    k_gemm<<<dim3(96, 4), 256>>>(p_AH, 192, 64,  d2_W2, 256, 64, o_xns,  256, 0, d2_b2, 0);
    k_gemm<<<dim3(96, 4), 256>>>(p_AH, 192, 128, d1_W2, 256, 64, o_xscf, 256, 0, d1_b2, 0);

    // s_ = hs @ hs^T (symmetric, triangular grid)
    k_syrk<<<4656, 256, (128 * 68 + 64 * 132) * sizeof(float)>>>(p_HS, o_s);
}

// round 2
// speedup vs baseline: 1.3997x; 1.3997x over previous
#include <cuda_runtime.h>
#include <cuda_bf16.h>
#include <mma.h>
#include <math.h>

using namespace nvcuda;

#define NN 12288
#define EE 393216
#define ET (EE + NN)

// ---------------- scratch (static __device__, no allocs) ----------------
__device__ int   g_degi[NN];
__device__ int   g_tmp[NN];
__device__ int   g_rowptr[NN + 1];
__device__ float g_dinv[NN];
__device__ int   g_cidx[ET];
__device__ float g_cval[ET];

__device__ float g_P1[NN * 128];   // [P1 | P1_cf]
__device__ float g_H1[NN * 128];   // relu(agg P1)+b1 for both
__device__ float g_Q [NN * 128];   // [H1a@W2 | H1b@W2]
__device__ float g_Z [NN * 128];   // [z | z_cf]
__device__ float g_ZS[NN * 96];    // [z_s | z_ns | z_s_cf]
__device__ float g_AZ[NN * 96];    // agg of ZS
__device__ float g_HD[NN * 192];   // [relu d1(z_s) | relu d2(z_ns) | relu d1(z_s_cf)]
__device__ float g_AH[NN * 192];   // agg of HD
__device__ float g_HS[NN * 64];    // hs
__device__ __nv_bfloat16 g_As[NN * 192];  // [hi|hi|lo]
__device__ __nv_bfloat16 g_Bs[NN * 192];  // [hi|lo|hi]

// ---------------- graph build ----------------
__global__ void k_zero2(void) {
    int i = blockIdx.x * blockDim.x + threadIdx.x;
    if (i < NN) g_degi[i] = 0;
    else if (i < 2 * NN) g_tmp[i - NN] = 0;
}

__global__ void k_deg(const int* __restrict__ ei) {
    int i = blockIdx.x * blockDim.x + threadIdx.x;
    if (i < EE) atomicAdd(&g_degi[ei[EE + i]], 1);
}

__global__ void k_dinv(void) {
    int i = blockIdx.x * blockDim.x + threadIdx.x;
    if (i < NN) g_dinv[i] = rsqrtf((float)(g_degi[i] + 1));
}

__global__ void k_scan(void) {  // 1 block, 1024 threads, 12 elems each, shfl scan
    __shared__ int ws[32];
    int t = threadIdx.x;
    int lane = t & 31, wid = t >> 5;
    int base = t * 12;
    int local[12];
    int s = 0;
#pragma unroll
    for (int i = 0; i < 12; i++) { local[i] = g_degi[base + i] + 1; s += local[i]; }
    int v = s;
#pragma unroll
    for (int off = 1; off < 32; off <<= 1) {
        int u = __shfl_up_sync(0xffffffffu, v, off);
        if (lane >= off) v += u;
    }
    if (lane == 31) ws[wid] = v;
    __syncthreads();
    if (t < 32) {
        int u = ws[t];
#pragma unroll
        for (int off = 1; off < 32; off <<= 1) {
            int w = __shfl_up_sync(0xffffffffu, u, off);
            if (t >= off) u += w;
        }
        ws[t] = u;
    }
    __syncthreads();
    int excl = v - s + (wid ? ws[wid - 1] : 0);
#pragma unroll
    for (int i = 0; i < 12; i++) { g_rowptr[base + i] = excl; excl += local[i]; }
    if (t == 1023) g_rowptr[NN] = excl;
}

__global__ void k_fill(const int* __restrict__ ei) {
    int i = blockIdx.x * blockDim.x + threadIdx.x;
    if (i < EE) {
        int s = ei[i], d = ei[EE + i];
        int p = g_rowptr[d] + atomicAdd(&g_tmp[d], 1);
        g_cidx[p] = s;
        g_cval[p] = g_dinv[s] * g_dinv[d];
    } else if (i < ET) {
        int nid = i - EE;
        int p = g_rowptr[nid] + atomicAdd(&g_tmp[nid], 1);
        g_cidx[p] = nid;
        g_cval[p] = g_dinv[nid] * g_dinv[nid];
    }
}

// ---------------- CSR SpMM: out[n,f] = sum_e val*H[src,f]  (+bias,relu) ----------------
template <int VT>
__global__ __launch_bounds__(256) void k_spmm(const float* __restrict__ H,
                                              float* __restrict__ out,
                                              const float* __restrict__ bias,
                                              int relu) {
    const int F = VT * 32;
    int warp = (blockIdx.x * blockDim.x + threadIdx.x) >> 5;
    int lane = threadIdx.x & 31;
    if (warp >= NN) return;
    float acc[VT];
#pragma unroll
    for (int i = 0; i < VT; i++) acc[i] = 0.f;
    int p0 = g_rowptr[warp], p1 = g_rowptr[warp + 1];
    for (int p = p0; p < p1; ++p) {
        int s = g_cidx[p];
        float v = g_cval[p];
        const float* hr = H + s * F;
#pragma unroll
        for (int i = 0; i < VT; i++) acc[i] += v * __ldg(hr + lane + i * 32);
    }
    float* o = out + warp * F;
#pragma unroll
    for (int i = 0; i < VT; i++) {
        float r = acc[i];
        if (bias) r += bias[(lane + i * 32) & 63];
        if (relu) r = fmaxf(r, 0.f);
        o[lane + i * 32] = r;
    }
}

// ---------------- generic small GEMM: C = act(A[:,aoff:aoff+K] @ B + bias) ----------------
__global__ __launch_bounds__(256) void k_gemm(const float* __restrict__ A, int lda, int aoff,
                                              const float* __restrict__ B, int ldb, int K,
                                              float* __restrict__ C, int ldc, int coff,
                                              const float* __restrict__ bias, int relu) {
    __shared__ float As[128 * 36];
    __shared__ float Bs[32 * 64];
    int r0 = blockIdx.x * 128;
    int c0 = blockIdx.y * 64;
    int t = threadIdx.x;
    int tx = t & 15, ty = t >> 4;
    float acc[8][4];
#pragma unroll
    for (int i = 0; i < 8; i++)
#pragma unroll
        for (int j = 0; j < 4; j++) acc[i][j] = 0.f;

    for (int kt = 0; kt < K; kt += 32) {
#pragma unroll
        for (int it = 0; it < 4; ++it) {
            int li = t + it * 256;
            int m = li >> 3;
            int kv = (li & 7) << 2;
            float4 v = *(const float4*)(A + (r0 + m) * lda + aoff + kt + kv);
            *(float4*)&As[m * 36 + kv] = v;
        }
#pragma unroll
        for (int it = 0; it < 2; ++it) {
            int li = t + it * 256;
            int kk = li >> 4;
            int nv = (li & 15) << 2;
            float4 v = *(const float4*)(B + (kt + kk) * ldb + c0 + nv);
            *(float4*)&Bs[kk * 64 + nv] = v;
        }
        __syncthreads();
#pragma unroll
        for (int k4 = 0; k4 < 32; k4 += 4) {
            float4 a4[8];
#pragma unroll
            for (int i = 0; i < 8; i++) a4[i] = *(const float4*)&As[(ty * 8 + i) * 36 + k4];
#pragma unroll
            for (int kk = 0; kk < 4; kk++) {
                float4 b = *(const float4*)&Bs[(k4 + kk) * 64 + tx * 4];
#pragma unroll
                for (int i = 0; i < 8; i++) {
                    float av = (kk == 0) ? a4[i].x : (kk == 1) ? a4[i].y : (kk == 2) ? a4[i].z : a4[i].w;
                    acc[i][0] += av * b.x;
                    acc[i][1] += av * b.y;
                    acc[i][2] += av * b.z;
                    acc[i][3] += av * b.w;
                }
            }
        }
        __syncthreads();
    }
    float bv[4] = {0.f, 0.f, 0.f, 0.f};
    if (bias) {
#pragma unroll
        for (int j = 0; j < 4; j++) bv[j] = bias[c0 + tx * 4 + j];
    }
#pragma unroll
    for (int i = 0; i < 8; i++) {
        float4 v;
        v.x = acc[i][0] + bv[0];
        v.y = acc[i][1] + bv[1];
        v.z = acc[i][2] + bv[2];
        v.w = acc[i][3] + bv[3];
        if (relu) {
            v.x = fmaxf(v.x, 0.f); v.y = fmaxf(v.y, 0.f);
            v.z = fmaxf(v.z, 0.f); v.w = fmaxf(v.w, 0.f);
        }
        *(float4*)(C + (r0 + ty * 8 + i) * ldc + coff + c0 + tx * 4) = v;
    }
}

// ---------------- elementwise helpers ----------------
__global__ void k_p1cf(const float* __restrict__ x, const float* __restrict__ W1) {
    int i = blockIdx.x * blockDim.x + threadIdx.x;
    if (i >= NN * 64) return;
    int r = i >> 6, m = i & 63;
    g_P1[r * 128 + 64 + m] = g_P1[r * 128 + m] + (1.f - 2.f * x[r * 256]) * W1[m];
}

__global__ void k_zsbuild(float* __restrict__ o_zs, float* __restrict__ o_zns) {
    int i = blockIdx.x * blockDim.x + threadIdx.x;
    if (i >= NN * 32) return;
    int r = i >> 5, c = i & 31;
    float zs   = g_Z[r * 128 + c];
    float zns  = g_Z[r * 128 + 32 + c];
    float zscf = g_Z[r * 128 + 64 + c];
    g_ZS[r * 96 + c] = zs;
    g_ZS[r * 96 + 32 + c] = zns;
    g_ZS[r * 96 + 64 + c] = zscf;
    o_zs[r * 32 + c] = zs;
    o_zns[r * 32 + c] = zns;
}

// split hs into bf16 hi/lo, build A'=[hi|hi|lo], B'=[hi|lo|hi]
__global__ void k_split(void) {
    int i = blockIdx.x * blockDim.x + threadIdx.x;
    if (i >= NN * 64) return;
    int r = i >> 6, c = i & 63;
    float x = g_HS[i];
    __nv_bfloat16 hi = __float2bfloat16_rn(x);
    __nv_bfloat16 lo = __float2bfloat16_rn(x - __bfloat162float(hi));
    g_As[r * 192 + c]       = hi;
    g_As[r * 192 + 64 + c]  = hi;
    g_As[r * 192 + 128 + c] = lo;
    g_Bs[r * 192 + c]       = hi;
    g_Bs[r * 192 + 64 + c]  = lo;
    g_Bs[r * 192 + 128 + c] = hi;
}

// ---------------- SYRK via bf16 tensor cores: C = A' B'^T  (K=192) ----------------
// triangular block grid (4656 blocks), tile 128x128; off-diag blocks also write transpose.
#define SYRK_LD 200   // padded K stride in elements (bf16)
__global__ __launch_bounds__(256, 2) void k_syrk_tc(float* __restrict__ C) {
    extern __shared__ __nv_bfloat16 sm[];
    __nv_bfloat16* As = sm;                   // 128 x SYRK_LD
    __nv_bfloat16* Bs = sm + 128 * SYRK_LD;   // 128 x SYRK_LD

    int t = blockIdx.x;
    float bf = 96.5f - sqrtf(96.5f * 96.5f - 2.0f * (float)t);
    int br = (int)bf;
    if (br < 0) br = 0;
    if (br > 95) br = 95;
    while (96 * br - (br * (br - 1)) / 2 > t) --br;
    while (96 * (br + 1) - ((br + 1) * br) / 2 <= t) ++br;
    int bc = br + (t - (96 * br - (br * (br - 1)) / 2));
    int r0 = br * 128, c0 = bc * 128;

    int tid = threadIdx.x;
    // load 128 rows x 192 bf16 (= 24 uint4 per row) for both tiles
#pragma unroll
    for (int it = 0; it < 12; ++it) {
        int li = tid + it * 256;           // 0..3071
        int row = li / 24;
        int seg = li % 24;
        uint4 va = *(const uint4*)&g_As[(r0 + row) * 192 + seg * 8];
        *(uint4*)&As[row * SYRK_LD + seg * 8] = va;
        uint4 vb = *(const uint4*)&g_Bs[(c0 + row) * 192 + seg * 8];
        *(uint4*)&Bs[row * SYRK_LD + seg * 8] = vb;
    }
    __syncthreads();

    int w = tid >> 5;
    int wr = w >> 2;          // 0..1  -> 64-row slab
    int wc = w & 3;           // 0..3  -> 32-col slab

    wmma::fragment<wmma::accumulator, 16, 16, 16, float> acc[4][2];
#pragma unroll
    for (int i = 0; i < 4; i++)
#pragma unroll
        for (int j = 0; j < 2; j++) wmma::fill_fragment(acc[i][j], 0.f);

#pragma unroll
    for (int k = 0; k < 12; ++k) {
        wmma::fragment<wmma::matrix_a, 16, 16, 16, __nv_bfloat16, wmma::row_major> af[4];
        wmma::fragment<wmma::matrix_b, 16, 16, 16, __nv_bfloat16, wmma::col_major> bfv[2];
#pragma unroll
        for (int i = 0; i < 4; i++)
            wmma::load_matrix_sync(af[i], As + (wr * 64 + 16 * i) * SYRK_LD + k * 16, SYRK_LD);
#pragma unroll
        for (int j = 0; j < 2; j++)
            wmma::load_matrix_sync(bfv[j], Bs + (wc * 32 + 16 * j) * SYRK_LD + k * 16, SYRK_LD);
#pragma unroll
        for (int i = 0; i < 4; i++)
#pragma unroll
            for (int j = 0; j < 2; j++)
                wmma::mma_sync(acc[i][j], af[i], bfv[j], acc[i][j]);
    }

#pragma unroll
    for (int i = 0; i < 4; i++)
#pragma unroll
        for (int j = 0; j < 2; j++) {
            int rr = r0 + wr * 64 + 16 * i;
            int cc = c0 + wc * 32 + 16 * j;
            wmma::store_matrix_sync(C + (size_t)rr * NN + cc, acc[i][j], NN, wmma::mem_row_major);
            if (br != bc)   // mirrored tile: store transpose
                wmma::store_matrix_sync(C + (size_t)cc * NN + rr, acc[i][j], NN, wmma::mem_col_major);
        }
}

// ---------------- launch ----------------
extern "C" void kernel_launch(void* const* d_in, const int* in_sizes, int n_in,
                              void* d_out, int out_size) {
    const float* x      = (const float*)d_in[0];
    const int*   ei     = (const int*)d_in[1];
    const float* enc_W1 = (const float*)d_in[2];
    const float* enc_b1 = (const float*)d_in[3];
    const float* enc_W2 = (const float*)d_in[4];
    const float* enc_b2 = (const float*)d_in[5];
    const float* d1_W1  = (const float*)d_in[6];
    const float* d1_b1  = (const float*)d_in[7];
    const float* d1_W2  = (const float*)d_in[8];
    const float* d1_b2  = (const float*)d_in[9];
    const float* d2_W1  = (const float*)d_in[10];
    const float* d2_b1  = (const float*)d_in[11];
    const float* d2_W2  = (const float*)d_in[12];
    const float* d2_b2  = (const float*)d_in[13];
    const float* s_W    = (const float*)d_in[14];
    const float* s_b    = (const float*)d_in[15];

    float* out     = (float*)d_out;
    float* o_zs    = out;
    float* o_zns   = out + NN * 32;
    float* o_xs    = out + NN * 64;
    float* o_xns   = o_xs + NN * 256;
    float* o_xscf  = o_xns + NN * 256;
    float* o_s     = o_xscf + NN * 256;

    float *p_P1, *p_H1, *p_Q, *p_Z, *p_ZS, *p_AZ, *p_HD, *p_AH, *p_HS;
    cudaGetSymbolAddress((void**)&p_P1, g_P1);
    cudaGetSymbolAddress((void**)&p_H1, g_H1);
    cudaGetSymbolAddress((void**)&p_Q,  g_Q);
    cudaGetSymbolAddress((void**)&p_Z,  g_Z);
    cudaGetSymbolAddress((void**)&p_ZS, g_ZS);
    cudaGetSymbolAddress((void**)&p_AZ, g_AZ);
    cudaGetSymbolAddress((void**)&p_HD, g_HD);
    cudaGetSymbolAddress((void**)&p_AH, g_AH);
    cudaGetSymbolAddress((void**)&p_HS, g_HS);

    const int syrk_smem = 2 * 128 * SYRK_LD * (int)sizeof(__nv_bfloat16);
    cudaFuncSetAttribute(k_syrk_tc, cudaFuncAttributeMaxDynamicSharedMemorySize, syrk_smem);

    // graph normalization + CSR
    k_zero2<<<(2 * NN + 255) / 256, 256>>>();
    k_deg<<<(EE + 255) / 256, 256>>>(ei);
    k_dinv<<<(NN + 255) / 256, 256>>>();
    k_scan<<<1, 1024>>>();
    k_fill<<<(ET + 255) / 256, 256>>>(ei);

    // encoder layer 1
    k_gemm<<<dim3(96, 1), 256>>>(x, 256, 0, enc_W1, 64, 256, p_P1, 128, 0, nullptr, 0);
    k_p1cf<<<(NN * 64 + 255) / 256, 256>>>(x, enc_W1);
    k_spmm<4><<<NN / 8, 256>>>(p_P1, p_H1, enc_b1, 1);

    // encoder layer 2
    k_gemm<<<dim3(96, 1), 256>>>(p_H1, 128, 0,  enc_W2, 64, 64, p_Q, 128, 0,  nullptr, 0);
    k_gemm<<<dim3(96, 1), 256>>>(p_H1, 128, 64, enc_W2, 64, 64, p_Q, 128, 64, nullptr, 0);
    k_spmm<4><<<NN / 8, 256>>>(p_Q, p_Z, enc_b2, 0);

    // split + batched z aggregation
    k_zsbuild<<<(NN * 32 + 255) / 256, 256>>>(o_zs, o_zns);
    k_spmm<3><<<NN / 8, 256>>>(p_ZS, p_AZ, nullptr, 0);

    // decoder first convs + structure head
    k_gemm<<<dim3(96, 1), 256>>>(p_AZ, 96, 0,  d1_W1, 64, 32, p_HD, 192, 0,   d1_b1, 1);
    k_gemm<<<dim3(96, 1), 256>>>(p_AZ, 96, 32, d2_W1, 64, 32, p_HD, 192, 64,  d2_b1, 1);
    k_gemm<<<dim3(96, 1), 256>>>(p_AZ, 96, 64, d1_W1, 64, 32, p_HD, 192, 128, d1_b1, 1);
    k_gemm<<<dim3(96, 1), 256>>>(p_AZ, 96, 32, s_W,   64, 32, p_HS, 64, 0,    s_b,   0);

    // hs split for tensor-core SYRK
    k_split<<<(NN * 64 + 255) / 256, 256>>>();

    // decoder second convs (aggregate at 64, then widen to 256)
    k_spmm<6><<<NN / 8, 256>>>(p_HD, p_AH, nullptr, 0);
    k_gemm<<<dim3(96, 4), 256>>>(p_AH, 192, 0,   d1_W2, 256, 64, o_xs,   256, 0, d1_b2, 0);
    k_gemm<<<dim3(96, 4), 256>>>(p_AH, 192, 64,  d2_W2, 256, 64, o_xns,  256, 0, d2_b2, 0);
    k_gemm<<<dim3(96, 4), 256>>>(p_AH, 192, 128, d1_W2, 256, 64, o_xscf, 256, 0, d1_b2, 0);

    // s_ = hs @ hs^T via bf16 tensor cores (symmetric, triangular grid)
    k_syrk_tc<<<4656, 256, syrk_smem>>>(o_s);
}

// round 3
// speedup vs baseline: 1.5887x; 1.1350x over previous
#include <cuda_runtime.h>
#include <cuda_bf16.h>
#include <mma.h>
#include <math.h>

using namespace nvcuda;

#define NN 12288
#define EE 393216
#define ET (EE + NN)

// ---------------- scratch (static __device__, no allocs) ----------------
__device__ int   g_degi[NN];
__device__ int   g_tmp[NN];
__device__ int   g_rowptr[NN + 1];
__device__ float g_dinv[NN];
__device__ int   g_cidx[ET];
__device__ float g_cval[ET];

__device__ float g_P1[NN * 128];   // [P1 | P1_cf]
__device__ float g_H1[NN * 128];   // relu(agg P1)+b1 for both
__device__ float g_Q [NN * 128];   // [H1a@W2 | H1b@W2]
__device__ float g_Z [NN * 128];   // [z | z_cf]
__device__ float g_ZS[NN * 96];    // [z_s | z_ns | z_s_cf]
__device__ float g_AZ[NN * 96];    // agg of ZS
__device__ float g_HD[NN * 192];   // [relu d1(z_s) | relu d2(z_ns) | relu d1(z_s_cf)]
__device__ float g_AH[NN * 192];   // agg of HD
__device__ float g_HS[NN * 64];    // hs
__device__ __nv_bfloat16 g_As[NN * 192];  // [hi|hi|lo]
__device__ __nv_bfloat16 g_Bs[NN * 192];  // [hi|lo|hi]

// ---------------- graph build ----------------
__global__ void k_zero2(void) {
    int i = blockIdx.x * blockDim.x + threadIdx.x;
    if (i < NN) g_degi[i] = 0;
    else if (i < 2 * NN) g_tmp[i - NN] = 0;
}

__global__ void k_deg(const int* __restrict__ ei) {
    int i = blockIdx.x * blockDim.x + threadIdx.x;
    if (i < EE) atomicAdd(&g_degi[ei[EE + i]], 1);
}

__global__ void k_dinv(void) {
    int i = blockIdx.x * blockDim.x + threadIdx.x;
    if (i < NN) g_dinv[i] = rsqrtf((float)(g_degi[i] + 1));
}

__global__ void k_scan(void) {  // 1 block, 1024 threads, 12 elems each, shfl scan
    __shared__ int ws[32];
    int t = threadIdx.x;
    int lane = t & 31, wid = t >> 5;
    int base = t * 12;
    int local[12];
    int s = 0;
#pragma unroll
    for (int i = 0; i < 12; i++) { local[i] = g_degi[base + i] + 1; s += local[i]; }
    int v = s;
#pragma unroll
    for (int off = 1; off < 32; off <<= 1) {
        int u = __shfl_up_sync(0xffffffffu, v, off);
        if (lane >= off) v += u;
    }
    if (lane == 31) ws[wid] = v;
    __syncthreads();
    if (t < 32) {
        int u = ws[t];
#pragma unroll
        for (int off = 1; off < 32; off <<= 1) {
            int w = __shfl_up_sync(0xffffffffu, u, off);
            if (t >= off) u += w;
        }
        ws[t] = u;
    }
    __syncthreads();
    int excl = v - s + (wid ? ws[wid - 1] : 0);
#pragma unroll
    for (int i = 0; i < 12; i++) { g_rowptr[base + i] = excl; excl += local[i]; }
    if (t == 1023) g_rowptr[NN] = excl;
}

__global__ void k_fill(const int* __restrict__ ei) {
    int i = blockIdx.x * blockDim.x + threadIdx.x;
    if (i < EE) {
        int s = ei[i], d = ei[EE + i];
        int p = g_rowptr[d] + atomicAdd(&g_tmp[d], 1);
        g_cidx[p] = s;
        g_cval[p] = g_dinv[s] * g_dinv[d];
    } else if (i < ET) {
        int nid = i - EE;
        int p = g_rowptr[nid] + atomicAdd(&g_tmp[nid], 1);
        g_cidx[p] = nid;
        g_cval[p] = g_dinv[nid] * g_dinv[nid];
    }
}

// ---------------- CSR SpMM: out[n,f] = sum_e val*H[src,f]  (+bias,relu) ----------------
template <int VT>
__global__ __launch_bounds__(256) void k_spmm(const float* __restrict__ H,
                                              float* __restrict__ out,
                                              const float* __restrict__ bias,
                                              int relu) {
    const int F = VT * 32;
    int warp = (blockIdx.x * blockDim.x + threadIdx.x) >> 5;
    int lane = threadIdx.x & 31;
    if (warp >= NN) return;
    float acc[VT];
#pragma unroll
    for (int i = 0; i < VT; i++) acc[i] = 0.f;
    int p0 = g_rowptr[warp], p1 = g_rowptr[warp + 1];
    for (int p = p0; p < p1; ++p) {
        int s = g_cidx[p];
        float v = g_cval[p];
        const float* hr = H + s * F;
#pragma unroll
        for (int i = 0; i < VT; i++) acc[i] += v * __ldg(hr + lane + i * 32);
    }
    float* o = out + warp * F;
#pragma unroll
    for (int i = 0; i < VT; i++) {
        float r = acc[i];
        if (bias) r += bias[(lane + i * 32) & 63];
        if (relu) r = fmaxf(r, 0.f);
        o[lane + i * 32] = r;
    }
}

// ---------------- batched small GEMM: per-op C = act(A[:,aoff:aoff+K] @ B + bias) ----------
struct GemmOp {
    const float* A; int lda; int aoff;
    const float* B; int ldb;
    float*       C; int ldc; int coff;
    const float* bias;
    int relu;
};
struct GemmBatch { GemmOp op[4]; };

__global__ __launch_bounds__(256) void k_gemmb(GemmBatch ops, int K) {
    __shared__ float As[128 * 36];
    __shared__ float Bs[32 * 64];
    const GemmOp& P = ops.op[blockIdx.z];
    const float* A = P.A;
    int lda = P.lda, aoff = P.aoff;
    int r0 = blockIdx.x * 128;
    int c0 = blockIdx.y * 64;
    int t = threadIdx.x;
    int tx = t & 15, ty = t >> 4;
    float acc[8][4];
#pragma unroll
    for (int i = 0; i < 8; i++)
#pragma unroll
        for (int j = 0; j < 4; j++) acc[i][j] = 0.f;

    for (int kt = 0; kt < K; kt += 32) {
#pragma unroll
        for (int it = 0; it < 4; ++it) {
            int li = t + it * 256;
            int m = li >> 3;
            int kv = (li & 7) << 2;
            float4 v = *(const float4*)(A + (r0 + m) * lda + aoff + kt + kv);
            *(float4*)&As[m * 36 + kv] = v;
        }
#pragma unroll
        for (int it = 0; it < 2; ++it) {
            int li = t + it * 256;
            int kk = li >> 4;
            int nv = (li & 15) << 2;
            float4 v = *(const float4*)(P.B + (kt + kk) * P.ldb + c0 + nv);
            *(float4*)&Bs[kk * 64 + nv] = v;
        }
        __syncthreads();
#pragma unroll
        for (int k4 = 0; k4 < 32; k4 += 4) {
            float4 a4[8];
#pragma unroll
            for (int i = 0; i < 8; i++) a4[i] = *(const float4*)&As[(ty * 8 + i) * 36 + k4];
#pragma unroll
            for (int kk = 0; kk < 4; kk++) {
                float4 b = *(const float4*)&Bs[(k4 + kk) * 64 + tx * 4];
#pragma unroll
                for (int i = 0; i < 8; i++) {
                    float av = (kk == 0) ? a4[i].x : (kk == 1) ? a4[i].y : (kk == 2) ? a4[i].z : a4[i].w;
                    acc[i][0] += av * b.x;
                    acc[i][1] += av * b.y;
                    acc[i][2] += av * b.z;
                    acc[i][3] += av * b.w;
                }
            }
        }
        __syncthreads();
    }
    float bv[4] = {0.f, 0.f, 0.f, 0.f};
    if (P.bias) {
#pragma unroll
        for (int j = 0; j < 4; j++) bv[j] = P.bias[c0 + tx * 4 + j];
    }
#pragma unroll
    for (int i = 0; i < 8; i++) {
        float4 v;
        v.x = acc[i][0] + bv[0];
        v.y = acc[i][1] + bv[1];
        v.z = acc[i][2] + bv[2];
        v.w = acc[i][3] + bv[3];
        if (P.relu) {
            v.x = fmaxf(v.x, 0.f); v.y = fmaxf(v.y, 0.f);
            v.z = fmaxf(v.z, 0.f); v.w = fmaxf(v.w, 0.f);
        }
        *(float4*)(P.C + (r0 + ty * 8 + i) * P.ldc + P.coff + c0 + tx * 4) = v;
    }
}

// ---------------- elementwise helpers ----------------
__global__ void k_p1cf(const float* __restrict__ x, const float* __restrict__ W1) {
    int i = blockIdx.x * blockDim.x + threadIdx.x;
    if (i >= NN * 64) return;
    int r = i >> 6, m = i & 63;
    g_P1[r * 128 + 64 + m] = g_P1[r * 128 + m] + (1.f - 2.f * x[r * 256]) * W1[m];
}

__global__ void k_zsbuild(float* __restrict__ o_zs, float* __restrict__ o_zns) {
    int i = blockIdx.x * blockDim.x + threadIdx.x;
    if (i >= NN * 32) return;
    int r = i >> 5, c = i & 31;
    float zs   = g_Z[r * 128 + c];
    float zns  = g_Z[r * 128 + 32 + c];
    float zscf = g_Z[r * 128 + 64 + c];
    g_ZS[r * 96 + c] = zs;
    g_ZS[r * 96 + 32 + c] = zns;
    g_ZS[r * 96 + 64 + c] = zscf;
    o_zs[r * 32 + c] = zs;
    o_zns[r * 32 + c] = zns;
}

// split hs into bf16 hi/lo, build A'=[hi|hi|lo], B'=[hi|lo|hi]
__global__ void k_split(void) {
    int i = blockIdx.x * blockDim.x + threadIdx.x;
    if (i >= NN * 64) return;
    int r = i >> 6, c = i & 63;
    float x = g_HS[i];
    __nv_bfloat16 hi = __float2bfloat16_rn(x);
    __nv_bfloat16 lo = __float2bfloat16_rn(x - __bfloat162float(hi));
    g_As[r * 192 + c]       = hi;
    g_As[r * 192 + 64 + c]  = hi;
    g_As[r * 192 + 128 + c] = lo;
    g_Bs[r * 192 + c]       = hi;
    g_Bs[r * 192 + 64 + c]  = lo;
    g_Bs[r * 192 + 128 + c] = hi;
}

// ---------------- SYRK via bf16 tensor cores: C = A' B'^T  (K=192) ----------------
#define SYRK_LD 200   // padded K stride in elements (bf16)
__global__ __launch_bounds__(256, 2) void k_syrk_tc(float* __restrict__ C) {
    extern __shared__ __nv_bfloat16 sm[];
    __nv_bfloat16* As = sm;                   // 128 x SYRK_LD
    __nv_bfloat16* Bs = sm + 128 * SYRK_LD;   // 128 x SYRK_LD

    int t = blockIdx.x;
    float bf = 96.5f - sqrtf(96.5f * 96.5f - 2.0f * (float)t);
    int br = (int)bf;
    if (br < 0) br = 0;
    if (br > 95) br = 95;
    while (96 * br - (br * (br - 1)) / 2 > t) --br;
    while (96 * (br + 1) - ((br + 1) * br) / 2 <= t) ++br;
    int bc = br + (t - (96 * br - (br * (br - 1)) / 2));
    int r0 = br * 128, c0 = bc * 128;

    int tid = threadIdx.x;
#pragma unroll
    for (int it = 0; it < 12; ++it) {
        int li = tid + it * 256;           // 0..3071
        int row = li / 24;
        int seg = li % 24;
        uint4 va = *(const uint4*)&g_As[(r0 + row) * 192 + seg * 8];
        *(uint4*)&As[row * SYRK_LD + seg * 8] = va;
        uint4 vb = *(const uint4*)&g_Bs[(c0 + row) * 192 + seg * 8];
        *(uint4*)&Bs[row * SYRK_LD + seg * 8] = vb;
    }
    __syncthreads();

    int w = tid >> 5;
    int wr = w >> 2;          // 0..1  -> 64-row slab
    int wc = w & 3;           // 0..3  -> 32-col slab

    wmma::fragment<wmma::accumulator, 16, 16, 16, float> acc[4][2];
#pragma unroll
    for (int i = 0; i < 4; i++)
#pragma unroll
        for (int j = 0; j < 2; j++) wmma::fill_fragment(acc[i][j], 0.f);

#pragma unroll
    for (int k = 0; k < 12; ++k) {
        wmma::fragment<wmma::matrix_a, 16, 16, 16, __nv_bfloat16, wmma::row_major> af[4];
        wmma::fragment<wmma::matrix_b, 16, 16, 16, __nv_bfloat16, wmma::col_major> bfv[2];
#pragma unroll
        for (int i = 0; i < 4; i++)
            wmma::load_matrix_sync(af[i], As + (wr * 64 + 16 * i) * SYRK_LD + k * 16, SYRK_LD);
#pragma unroll
        for (int j = 0; j < 2; j++)
            wmma::load_matrix_sync(bfv[j], Bs + (wc * 32 + 16 * j) * SYRK_LD + k * 16, SYRK_LD);
#pragma unroll
        for (int i = 0; i < 4; i++)
#pragma unroll
            for (int j = 0; j < 2; j++)
                wmma::mma_sync(acc[i][j], af[i], bfv[j], acc[i][j]);
    }

#pragma unroll
    for (int i = 0; i < 4; i++)
#pragma unroll
        for (int j = 0; j < 2; j++) {
            int rr = r0 + wr * 64 + 16 * i;
            int cc = c0 + wc * 32 + 16 * j;
            wmma::store_matrix_sync(C + (size_t)rr * NN + cc, acc[i][j], NN, wmma::mem_row_major);
            if (br != bc)   // mirrored tile: store transpose
                wmma::store_matrix_sync(C + (size_t)cc * NN + rr, acc[i][j], NN, wmma::mem_col_major);
        }
}

// ---------------- launch ----------------
extern "C" void kernel_launch(void* const* d_in, const int* in_sizes, int n_in,
                              void* d_out, int out_size) {
    const float* x      = (const float*)d_in[0];
    const int*   ei     = (const int*)d_in[1];
    const float* enc_W1 = (const float*)d_in[2];
    const float* enc_b1 = (const float*)d_in[3];
    const float* enc_W2 = (const float*)d_in[4];
    const float* enc_b2 = (const float*)d_in[5];
    const float* d1_W1  = (const float*)d_in[6];
    const float* d1_b1  = (const float*)d_in[7];
    const float* d1_W2  = (const float*)d_in[8];
    const float* d1_b2  = (const float*)d_in[9];
    const float* d2_W1  = (const float*)d_in[10];
    const float* d2_b1  = (const float*)d_in[11];
    const float* d2_W2  = (const float*)d_in[12];
    const float* d2_b2  = (const float*)d_in[13];
    const float* s_W    = (const float*)d_in[14];
    const float* s_b    = (const float*)d_in[15];

    float* out     = (float*)d_out;
    float* o_zs    = out;
    float* o_zns   = out + NN * 32;
    float* o_xs    = out + NN * 64;
    float* o_xns   = o_xs + NN * 256;
    float* o_xscf  = o_xns + NN * 256;
    float* o_s     = o_xscf + NN * 256;

    float *p_P1, *p_H1, *p_Q, *p_Z, *p_ZS, *p_AZ, *p_HD, *p_AH, *p_HS;
    cudaGetSymbolAddress((void**)&p_P1, g_P1);
    cudaGetSymbolAddress((void**)&p_H1, g_H1);
    cudaGetSymbolAddress((void**)&p_Q,  g_Q);
    cudaGetSymbolAddress((void**)&p_Z,  g_Z);
    cudaGetSymbolAddress((void**)&p_ZS, g_ZS);
    cudaGetSymbolAddress((void**)&p_AZ, g_AZ);
    cudaGetSymbolAddress((void**)&p_HD, g_HD);
    cudaGetSymbolAddress((void**)&p_AH, g_AH);
    cudaGetSymbolAddress((void**)&p_HS, g_HS);

    const int syrk_smem = 2 * 128 * SYRK_LD * (int)sizeof(__nv_bfloat16);
    cudaFuncSetAttribute(k_syrk_tc, cudaFuncAttributeMaxDynamicSharedMemorySize, syrk_smem);

    // one-time side stream + events for graph fork/join
    static cudaStream_t s1 = nullptr;
    static cudaEvent_t evF0, evJ0, evF1, evJ1;
    if (!s1) {
        cudaStreamCreateWithFlags(&s1, cudaStreamNonBlocking);
        cudaEventCreateWithFlags(&evF0, cudaEventDisableTiming);
        cudaEventCreateWithFlags(&evJ0, cudaEventDisableTiming);
        cudaEventCreateWithFlags(&evF1, cudaEventDisableTiming);
        cudaEventCreateWithFlags(&evJ1, cudaEventDisableTiming);
    }

    // ---- fork A: encoder layer-1 GEMM on s1, concurrent with graph build ----
    cudaEventRecord(evF0, 0);
    cudaStreamWaitEvent(s1, evF0, 0);
    {
        GemmBatch gb{};
        gb.op[0] = { x, 256, 0, enc_W1, 64, p_P1, 128, 0, nullptr, 0 };
        k_gemmb<<<dim3(96, 1, 1), 256, 0, s1>>>(gb, 256);
    }
    k_p1cf<<<(NN * 64 + 255) / 256, 256, 0, s1>>>(x, enc_W1);
    cudaEventRecord(evJ0, s1);

    // ---- stream 0: graph normalization + CSR ----
    k_zero2<<<(2 * NN + 255) / 256, 256>>>();
    k_deg<<<(EE + 255) / 256, 256>>>(ei);
    k_dinv<<<(NN + 255) / 256, 256>>>();
    k_scan<<<1, 1024>>>();
    k_fill<<<(ET + 255) / 256, 256>>>(ei);
    cudaStreamWaitEvent(0, evJ0, 0);   // join A

    // encoder layer 1 aggregation
    k_spmm<4><<<NN / 8, 256>>>(p_P1, p_H1, enc_b1, 1);

    // encoder layer 2 (2 GEMMs batched)
    {
        GemmBatch gb{};
        gb.op[0] = { p_H1, 128, 0,  enc_W2, 64, p_Q, 128, 0,  nullptr, 0 };
        gb.op[1] = { p_H1, 128, 64, enc_W2, 64, p_Q, 128, 64, nullptr, 0 };
        k_gemmb<<<dim3(96, 1, 2), 256>>>(gb, 64);
    }
    k_spmm<4><<<NN / 8, 256>>>(p_Q, p_Z, enc_b2, 0);

    // split + batched z aggregation
    k_zsbuild<<<(NN * 32 + 255) / 256, 256>>>(o_zs, o_zns);
    k_spmm<3><<<NN / 8, 256>>>(p_ZS, p_AZ, nullptr, 0);

    // decoder first convs + structure head (4 GEMMs batched)
    {
        GemmBatch gb{};
        gb.op[0] = { p_AZ, 96, 0,  d1_W1, 64, p_HD, 192, 0,   d1_b1, 1 };
        gb.op[1] = { p_AZ, 96, 32, d2_W1, 64, p_HD, 192, 64,  d2_b1, 1 };
        gb.op[2] = { p_AZ, 96, 64, d1_W1, 64, p_HD, 192, 128, d1_b1, 1 };
        gb.op[3] = { p_AZ, 96, 32, s_W,   64, p_HS, 64,  0,   s_b,   0 };
        k_gemmb<<<dim3(96, 1, 4), 256>>>(gb, 32);
    }

    // ---- fork B: SYRK path on s1, concurrent with decoder tail ----
    cudaEventRecord(evF1, 0);
    cudaStreamWaitEvent(s1, evF1, 0);
    k_split<<<(NN * 64 + 255) / 256, 256, 0, s1>>>();
    k_syrk_tc<<<4656, 256, syrk_smem, s1>>>(o_s);
    cudaEventRecord(evJ1, s1);

    // decoder second convs (aggregate at 64, then widen to 256; 3 GEMMs batched)
    k_spmm<6><<<NN / 8, 256>>>(p_HD, p_AH, nullptr, 0);
    {
        GemmBatch gb{};
        gb.op[0] = { p_AH, 192, 0,   d1_W2, 256, o_xs,   256, 0, d1_b2, 0 };
        gb.op[1] = { p_AH, 192, 64,  d2_W2, 256, o_xns,  256, 0, d2_b2, 0 };
        gb.op[2] = { p_AH, 192, 128, d1_W2, 256, o_xscf, 256, 0, d1_b2, 0 };
        k_gemmb<<<dim3(96, 4, 3), 256>>>(gb, 64);
    }

    cudaStreamWaitEvent(0, evJ1, 0);   // join B
}